// round 7
// baseline (speedup 1.0000x reference)
#include <cuda_runtime.h>

#define BATCH 16
#define D 128
#define NN 16
#define E 120
#define OUTB (256 * 256)

// Inter-kernel scratch: partial P sums per 16-row d-chunk.
// g_Pp{1,2}[b][chunk][i*16+j] = sum_{d in chunk} Fs[d][i] * (W_m @ Ft)[d][j]
__device__ float g_Pp1[BATCH][8][256];
__device__ float g_Pp2[BATCH][8][256];

// ---------------------------------------------------------------------------
// kA: per block (b, m, chunk of 16 W-rows):
//   ws = relu(lam_m[rows] + lam_m^T[rows])     (smem, two coalesced passes)
//   tmp[dloc][j] = sum_d' ws[dloc][d'] * Ft[b][d'][j]
//   Pp[i][j]     = sum_dloc Fs[b][c0+dloc][i] * tmp[dloc][j]   -> g_Pp
// grid: 256 = b*16 + m*8 + chunk, 256 threads
// ---------------------------------------------------------------------------
__global__ void kA(const float* __restrict__ Fs,
                   const float* __restrict__ Ft,
                   const float* __restrict__ lam1,
                   const float* __restrict__ lam2) {
    __shared__ float Fts[D * NN];     // [d'][j]
    __shared__ float ws[16][132];     // padded: conflict-free float4 reads
    __shared__ float Fss[16][17];     // [dloc][i]
    __shared__ float tmps[16][17];    // [dloc][j]

    const int b     = blockIdx.x >> 4;
    const int m     = (blockIdx.x >> 3) & 1;
    const int chunk = blockIdx.x & 7;
    const int c0    = chunk * 16;
    const int t     = threadIdx.x;

    const float* lam = m ? lam2 : lam1;
    const float* ft  = Ft + b * D * NN;
    const float* fs  = Fs + b * D * NN;

    for (int idx = t; idx < D * NN; idx += 256) Fts[idx] = ft[idx];

    // Fs chunk rows: 256 consecutive floats, fully coalesced
    Fss[t >> 4][t & 15] = fs[c0 * NN + t];

    // pass 1: direct lam rows, coalesced
    for (int idx = t; idx < 16 * D; idx += 256) {
        const int d  = idx >> 7;
        const int dp = idx & 127;
        ws[d][dp] = lam[(c0 + d) * D + dp];
    }
    __syncthreads();

    // pass 2: transposed term + relu (each warp touches 2 contiguous 64B runs)
    for (int idx = t; idx < 16 * D; idx += 256) {
        const int d  = idx & 15;
        const int dp = idx >> 4;
        const float v = ws[d][dp] + lam[dp * D + c0 + d];
        ws[d][dp] = v > 0.f ? v : 0.f;
    }
    __syncthreads();

    // tmp[dloc][j] = ws[dloc][:] . Fts[:][j]
    const int j    = t & 15;
    const int dloc = t >> 4;
    const float4* wv = reinterpret_cast<const float4*>(ws[dloc]);

    float a0 = 0.f, a1 = 0.f;
#pragma unroll
    for (int q = 0; q < D / 8; q++) {
        const float4 wa = wv[2 * q];
        const float4 wb = wv[2 * q + 1];
        const int base = 8 * q * NN + j;
        a0 += wa.x * Fts[base + 0 * NN] + wa.y * Fts[base + 1 * NN]
            + wa.z * Fts[base + 2 * NN] + wa.w * Fts[base + 3 * NN];
        a1 += wb.x * Fts[base + 4 * NN] + wb.y * Fts[base + 5 * NN]
            + wb.z * Fts[base + 6 * NN] + wb.w * Fts[base + 7 * NN];
    }
    tmps[dloc][j] = a0 + a1;
    __syncthreads();

    // Pp[i][jj] = sum_d Fss[d][i] * tmps[d][jj]  (thread re-mapped to (i,jj))
    const int i  = t >> 4;
    const int jj = t & 15;
    float p = 0.f;
#pragma unroll
    for (int d = 0; d < 16; d++)
        p += Fss[d][i] * tmps[d][jj];

    float* pp = m ? &g_Pp2[b][chunk][0] : &g_Pp1[b][chunk][0];
    pp[t] = p;
}

// ---------------------------------------------------------------------------
// kB: per block (b, i2p, row-group of 4 i1p):
//   P1/P2[t] = sum_{chunk} g_Pp{1,2}[b][chunk][t]   (8 coalesced loads each)
//   mp[j]    = sum_d Us[d][i2p] * Ut[d][j]
//   both[e]  = (A_src>0)&(A_tgt>0)
//   write 4 output rows; exactly one float4 store per thread (coalesced).
// grid: 1024 = b*64 + i2p*4 + rg, 256 threads
// ---------------------------------------------------------------------------
__global__ void kB(const float* __restrict__ Us,
                   const float* __restrict__ Ut,
                   const int* __restrict__ As,
                   const int* __restrict__ At,
                   float* __restrict__ out) {
    __shared__ float P1s[256];
    __shared__ float P2s[256];
    __shared__ float mps[16];
    __shared__ int   boths[E];

    const int b   = blockIdx.x >> 6;
    const int i2p = (blockIdx.x >> 2) & 15;
    const int rg  = blockIdx.x & 3;
    const int t   = threadIdx.x;

    // reduce partials (16 independent coalesced loads)
    {
        float s1 = 0.f, s2 = 0.f;
#pragma unroll
        for (int c = 0; c < 8; c++) {
            s1 += g_Pp1[b][c][t];
            s2 += g_Pp2[b][c][t];
        }
        P1s[t] = s1;
        P2s[t] = s2;
    }

    if (t < E)
        boths[t] = (As[b * E + t] > 0) && (At[b * E + t] > 0);

    if (t < 16) {
        float mp = 0.f;
#pragma unroll
        for (int d = 0; d < NN; d++)
            mp += Us[b * 256 + d * 16 + i2p] * Ut[b * 256 + d * 16 + t];
        mps[t] = mp;
    }
    __syncthreads();

    // write: i1p = rg*4 + (t>>6); 64 threads cover one 256-wide row (q0=tq*4)
    const int i1p = rg * 4 + (t >> 6);
    const int tq  = t & 63;
    const int q0  = tq * 4;
    const int i2q = q0 >> 4;
    const int i1q0 = q0 & 15;
    const int p   = i2p * 16 + i1p;

    int e2ok = 0;
    if (i2p < i2q) {
        const int e2 = i2p * (29 - i2p) / 2 + i2q - 1;
        e2ok = boths[e2];
    }

    const float a_p1   = P1s[p];                    // P1[i2p,i1p]
    const float c_p2   = P2s[i2q * 16 + i1p];       // P2[i2q,i1p]
    const int   ebase1 = i1p * (29 - i1p) / 2 - 1;  // e1 = ebase1 + i1q

    float4 v;
    float* vp = &v.x;
#pragma unroll
    for (int k = 0; k < 4; k++) {
        const int i1q = i1q0 + k;
        float val = (i2q == i2p && i1q == i1p) ? mps[i1p] : 0.f;
        if (e2ok && i1p < i1q && boths[ebase1 + i1q])
            val += a_p1 + P2s[i2p * 16 + i1q] + c_p2 + P1s[i2q * 16 + i1q];
        vp[k] = val;
    }
    *reinterpret_cast<float4*>(out + b * OUTB + p * 256 + q0) = v;
}

extern "C" void kernel_launch(void* const* d_in, const int* in_sizes, int n_in,
                              void* d_out, int out_size) {
    const int*   As   = (const int*)d_in[0];
    const int*   At   = (const int*)d_in[1];
    const float* Fs   = (const float*)d_in[2];
    const float* Ft   = (const float*)d_in[3];
    const float* Us   = (const float*)d_in[4];
    const float* Ut   = (const float*)d_in[5];
    const float* lam1 = (const float*)d_in[6];
    const float* lam2 = (const float*)d_in[7];
    float* out = (float*)d_out;

    kA<<<256, 256>>>(Fs, Ft, lam1, lam2);
    kB<<<1024, 256>>>(Us, Ut, As, At, out);
}

// round 9
// speedup vs baseline: 1.4871x; 1.4871x over previous
#include <cuda_runtime.h>

#define BATCH 16
#define D 128
#define NN 16
#define E 120
#define OUTB (256 * 256)
#define GRID 256

// Scratch: partial P sums per 16-row d-chunk.
// g_Pp{1,2}[b][chunk][i*16+j] = sum_{d in chunk} Fs[d][i] * (W_m @ Ft)[d][j]
__device__ float g_Pp1[BATCH][8][256];
__device__ float g_Pp2[BATCH][8][256];
__device__ int   g_cnt_a;   // barrier arrive counter (reset each launch)
__device__ int   g_cnt_b;   // barrier depart counter (reset each launch)

// ---------------------------------------------------------------------------
// Single persistent kernel.
// Phase A: block (b, m, chunk) -> g_Pp partials (R5-style kA).
// Grid-wide barrier (two-counter, self-resetting -> graph-replay safe).
// Phase B: block (b, i2p) -> reduce partials, build tables, write 16 rows.
// ---------------------------------------------------------------------------
__global__ void __launch_bounds__(256, 8)
kFused(const float* __restrict__ Fs,
       const float* __restrict__ Ft,
       const float* __restrict__ Us,
       const float* __restrict__ Ut,
       const int* __restrict__ As,
       const int* __restrict__ At,
       const float* __restrict__ lam1,
       const float* __restrict__ lam2,
       float* __restrict__ out) {
    __shared__ float Fts[D * NN];     // [d'][j]
    __shared__ float ws[16][132];     // padded: conflict-free float4 reads
    __shared__ float Fss[16][17];     // [dloc][i]
    __shared__ float tmps[16][17];    // [dloc][j]
    __shared__ float P1s[256];
    __shared__ float P2s[256];
    __shared__ float mps[16];
    __shared__ int   boths[E];

    const int t = threadIdx.x;

    // ======================= Phase A =======================
    {
        const int b     = blockIdx.x >> 4;
        const int m     = (blockIdx.x >> 3) & 1;
        const int chunk = blockIdx.x & 7;
        const int c0    = chunk * 16;

        const float* lam = m ? lam2 : lam1;
        const float* ft  = Ft + b * D * NN;
        const float* fs  = Fs + b * D * NN;

        for (int idx = t; idx < D * NN; idx += 256) Fts[idx] = ft[idx];

        // Fs chunk rows: 256 consecutive floats, fully coalesced
        Fss[t >> 4][t & 15] = fs[c0 * NN + t];

        // pass 1: direct lam rows, coalesced
        for (int idx = t; idx < 16 * D; idx += 256) {
            const int d  = idx >> 7;
            const int dp = idx & 127;
            ws[d][dp] = lam[(c0 + d) * D + dp];
        }
        __syncthreads();

        // pass 2: transposed term + relu (2 contiguous 64B runs per warp)
        for (int idx = t; idx < 16 * D; idx += 256) {
            const int d  = idx & 15;
            const int dp = idx >> 4;
            const float v = ws[d][dp] + lam[dp * D + c0 + d];
            ws[d][dp] = v > 0.f ? v : 0.f;
        }
        __syncthreads();

        // tmp[dloc][j] = ws[dloc][:] . Fts[:][j]
        const int j    = t & 15;
        const int dloc = t >> 4;
        const float4* wv = reinterpret_cast<const float4*>(ws[dloc]);

        float a0 = 0.f, a1 = 0.f;
#pragma unroll
        for (int q = 0; q < D / 8; q++) {
            const float4 wa = wv[2 * q];
            const float4 wb = wv[2 * q + 1];
            const int base = 8 * q * NN + j;
            a0 += wa.x * Fts[base + 0 * NN] + wa.y * Fts[base + 1 * NN]
                + wa.z * Fts[base + 2 * NN] + wa.w * Fts[base + 3 * NN];
            a1 += wb.x * Fts[base + 4 * NN] + wb.y * Fts[base + 5 * NN]
                + wb.z * Fts[base + 6 * NN] + wb.w * Fts[base + 7 * NN];
        }
        tmps[dloc][j] = a0 + a1;
        __syncthreads();

        // Pp[i][jj] = sum_d Fss[d][i] * tmps[d][jj]
        const int i  = t >> 4;
        const int jj = t & 15;
        float p = 0.f;
#pragma unroll
        for (int d = 0; d < 16; d++)
            p += Fss[d][i] * tmps[d][jj];

        float* pp = m ? &g_Pp2[b][chunk][0] : &g_Pp1[b][chunk][0];
        pp[t] = p;
    }

    // ================== Grid-wide barrier ==================
    __syncthreads();
    if (t == 0) {
        __threadfence();                       // publish g_Pp
        atomicAdd(&g_cnt_a, 1);
        volatile int* ca = &g_cnt_a;
        while (*ca < GRID) __nanosleep(64);
        __threadfence();                       // acquire others' g_Pp
        const int rb = atomicAdd(&g_cnt_b, 1);
        if (rb == GRID - 1) {                  // last out resets for replay
            atomicExch(&g_cnt_a, 0);
            atomicExch(&g_cnt_b, 0);
        }
    }
    __syncthreads();

    // ======================= Phase B =======================
    {
        const int b   = blockIdx.x >> 4;
        const int i2p = blockIdx.x & 15;

        // reduce partials (hot in L2)
        float s1 = 0.f, s2 = 0.f;
#pragma unroll
        for (int c = 0; c < 8; c++) {
            s1 += g_Pp1[b][c][t];
            s2 += g_Pp2[b][c][t];
        }
        P1s[t] = s1;
        P2s[t] = s2;

        if (t < E)
            boths[t] = (As[b * E + t] > 0) && (At[b * E + t] > 0);

        if (t < 16) {
            float mp = 0.f;
#pragma unroll
            for (int d = 0; d < NN; d++)
                mp += Us[b * 256 + d * 16 + i2p] * Ut[b * 256 + d * 16 + t];
            mps[t] = mp;
        }
        __syncthreads();

        // write 16 rows x 256 cols: i1p = t>>4, tq = t&15, 4 float4 stores
        const int i1p = t >> 4;
        const int tq  = t & 15;
        const int p   = i2p * 16 + i1p;

        const float a_p1   = P1s[p];                    // P1[i2p,i1p]
        const int   ebase1 = i1p * (29 - i1p) / 2 - 1;  // e1 = ebase1 + i1q

        float* orow = out + b * OUTB + p * 256;

#pragma unroll
        for (int s = 0; s < 4; s++) {
            const int q0   = s * 64 + tq * 4;
            const int i2q  = q0 >> 4;
            const int i1q0 = q0 & 15;

            int e2ok = 0;
            if (i2p < i2q) {
                const int e2 = i2p * (29 - i2p) / 2 + i2q - 1;
                e2ok = boths[e2];
            }
            const float c_p2 = P2s[i2q * 16 + i1p];     // P2[i2q,i1p]

            float4 v;
            float* vp = &v.x;
#pragma unroll
            for (int k = 0; k < 4; k++) {
                const int i1q = i1q0 + k;
                float val = (i2q == i2p && i1q == i1p) ? mps[i1p] : 0.f;
                if (e2ok && i1p < i1q && boths[ebase1 + i1q])
                    val += a_p1 + P2s[i2p * 16 + i1q] + c_p2
                         + P1s[i2q * 16 + i1q];
                vp[k] = val;
            }
            *reinterpret_cast<float4*>(orow + q0) = v;
        }
    }
}

extern "C" void kernel_launch(void* const* d_in, const int* in_sizes, int n_in,
                              void* d_out, int out_size) {
    const int*   As   = (const int*)d_in[0];
    const int*   At   = (const int*)d_in[1];
    const float* Fs   = (const float*)d_in[2];
    const float* Ft   = (const float*)d_in[3];
    const float* Us   = (const float*)d_in[4];
    const float* Ut   = (const float*)d_in[5];
    const float* lam1 = (const float*)d_in[6];
    const float* lam2 = (const float*)d_in[7];
    float* out = (float*)d_out;

    kFused<<<GRID, 256>>>(Fs, Ft, Us, Ut, As, At, lam1, lam2, out);
}

// round 10
// speedup vs baseline: 1.8917x; 1.2720x over previous
#include <cuda_runtime.h>

#define BATCH 16
#define D 128
#define NN 16
#define E 120
#define OUTB (256 * 256)
#define GRID 256

// Scratch: partial P sums per 16-row d-chunk.
// g_Pp{1,2}[b][chunk][i*16+j] = sum_{d in chunk} Fs[d][i] * (W_m @ Ft)[d][j]
__device__ float g_Pp1[BATCH][8][256];
__device__ float g_Pp2[BATCH][8][256];
__device__ int   g_cnt_a[BATCH];   // per-batch arrive counters
__device__ int   g_cnt_b[BATCH];   // per-batch depart counters (for reset)

// ---------------------------------------------------------------------------
// Single persistent kernel, per-batch synchronization.
// Phase A: block (b, m, chunk) -> g_Pp partials. All gmem loads front-batched.
// Arrive on per-batch counter, then do phase-B-independent work (both, Mp row)
// while other blocks of the batch finish, then spin-wait for 16 arrivals.
// Phase B: block (b, i2p) -> reduce partials, write 16 output rows.
// ---------------------------------------------------------------------------
__global__ void __launch_bounds__(256, 4)
kFused(const float* __restrict__ Fs,
       const float* __restrict__ Ft,
       const float* __restrict__ Us,
       const float* __restrict__ Ut,
       const int* __restrict__ As,
       const int* __restrict__ At,
       const float* __restrict__ lam1,
       const float* __restrict__ lam2,
       float* __restrict__ out) {
    __shared__ float Fts[D * NN];     // [d'][j]
    __shared__ float ws[16][132];     // padded: conflict-free float4 reads
    __shared__ float Fss[16][17];     // [dloc][i]
    __shared__ float tmps[16][17];    // [dloc][j]
    __shared__ float P1s[256];
    __shared__ float P2s[256];
    __shared__ float mps[16];
    __shared__ int   boths[E];

    const int t   = threadIdx.x;
    const int b   = blockIdx.x >> 4;
    const int m   = (blockIdx.x >> 3) & 1;
    const int c0  = (blockIdx.x & 7) * 16;
    const int i2p = blockIdx.x & 15;           // phase-B role

    // ============ Phase A: front-batched loads ============
    const float* lam = m ? lam2 : lam1;
    const float* ft  = Ft + b * D * NN;
    const float* fs  = Fs + b * D * NN;

    const float4* ft4  = reinterpret_cast<const float4*>(ft);
    const float4* lam4 = reinterpret_cast<const float4*>(lam + c0 * D);

    // issue ALL independent global loads (MLP ~13) before any sync
    const float4 rf0 = ft4[t];                 // Ft first half
    const float4 rf1 = ft4[t + 256];           // Ft second half
    const float4 rw0 = lam4[t];                // lam pass-1 rows
    const float4 rw1 = lam4[t + 256];
    const float  rfs = fs[c0 * NN + t];        // Fs chunk
    float r2[8];                               // lam pass-2 (transposed term)
    {
        const int d  = t & 15;
        const int dp = t >> 4;
#pragma unroll
        for (int k = 0; k < 8; k++)
            r2[k] = lam[(dp + 16 * k) * D + c0 + d];
    }

    // stash pass-1 + Ft + Fs into smem
    *reinterpret_cast<float4*>(&Fts[4 * t])         = rf0;
    *reinterpret_cast<float4*>(&Fts[4 * (t + 256)]) = rf1;
    {
        const int e0 = 4 * t;                  // element index in 16x128 tile
        ws[e0 >> 7][e0 & 127]       = rw0.x;   // keep padded layout
        ws[e0 >> 7][(e0 & 127) + 1] = rw0.y;
        ws[e0 >> 7][(e0 & 127) + 2] = rw0.z;
        ws[e0 >> 7][(e0 & 127) + 3] = rw0.w;
        const int e1 = 4 * (t + 256);
        ws[e1 >> 7][e1 & 127]       = rw1.x;
        ws[e1 >> 7][(e1 & 127) + 1] = rw1.y;
        ws[e1 >> 7][(e1 & 127) + 2] = rw1.z;
        ws[e1 >> 7][(e1 & 127) + 3] = rw1.w;
    }
    Fss[t >> 4][t & 15] = rfs;
    __syncthreads();

    // pass-2 fixup: ws = relu(ws + lam^T term)  (smem-only)
    {
        const int d  = t & 15;
        const int dp = t >> 4;
#pragma unroll
        for (int k = 0; k < 8; k++) {
            const float v = ws[d][dp + 16 * k] + r2[k];
            ws[d][dp + 16 * k] = v > 0.f ? v : 0.f;
        }
    }
    __syncthreads();

    // tmp[dloc][j] = ws[dloc][:] . Fts[:][j]
    {
        const int j    = t & 15;
        const int dloc = t >> 4;
        const float4* wv = reinterpret_cast<const float4*>(ws[dloc]);

        float a0 = 0.f, a1 = 0.f;
#pragma unroll
        for (int q = 0; q < D / 8; q++) {
            const float4 wa = wv[2 * q];
            const float4 wb = wv[2 * q + 1];
            const int base = 8 * q * NN + j;
            a0 += wa.x * Fts[base + 0 * NN] + wa.y * Fts[base + 1 * NN]
                + wa.z * Fts[base + 2 * NN] + wa.w * Fts[base + 3 * NN];
            a1 += wb.x * Fts[base + 4 * NN] + wb.y * Fts[base + 5 * NN]
                + wb.z * Fts[base + 6 * NN] + wb.w * Fts[base + 7 * NN];
        }
        tmps[dloc][j] = a0 + a1;
    }
    __syncthreads();

    // Pp[i][jj] = sum_d Fss[d][i] * tmps[d][jj], publish partials
    {
        const int i  = t >> 4;
        const int jj = t & 15;
        float p = 0.f;
#pragma unroll
        for (int d = 0; d < 16; d++)
            p += Fss[d][i] * tmps[d][jj];

        float* pp = m ? &g_Pp2[b][blockIdx.x & 7][0]
                      : &g_Pp1[b][blockIdx.x & 7][0];
        pp[t] = p;
    }
    __syncthreads();

    // arrive early on per-batch counter
    if (t == 0) {
        __threadfence();
        atomicAdd(&g_cnt_a[b], 1);
    }

    // ====== phase-B-independent work, overlapped with the wait ======
    if (t < E)
        boths[t] = (As[b * E + t] > 0) && (At[b * E + t] > 0);

    if (t < 16) {
        float mp = 0.f;
#pragma unroll
        for (int d = 0; d < NN; d++)
            mp += Us[b * 256 + d * 16 + i2p] * Ut[b * 256 + d * 16 + t];
        mps[t] = mp;
    }

    // ============ per-batch wait (16 arrivals) ============
    if (t == 0) {
        volatile int* ca = &g_cnt_a[b];
        while (*ca < 16) __nanosleep(32);
        __threadfence();
        const int rb = atomicAdd(&g_cnt_b[b], 1);
        if (rb == 15) {                        // last out resets for replay
            atomicExch(&g_cnt_a[b], 0);
            atomicExch(&g_cnt_b[b], 0);
        }
    }
    __syncthreads();

    // ============ Phase B ============
    {
        float s1 = 0.f, s2 = 0.f;
#pragma unroll
        for (int c = 0; c < 8; c++) {
            s1 += g_Pp1[b][c][t];
            s2 += g_Pp2[b][c][t];
        }
        P1s[t] = s1;
        P2s[t] = s2;
    }
    __syncthreads();

    // write 16 rows x 256 cols: i1p = t>>4, tq = t&15, 4 float4 stores
    {
        const int i1p = t >> 4;
        const int tq  = t & 15;
        const int p   = i2p * 16 + i1p;

        const float a_p1   = P1s[p];                    // P1[i2p,i1p]
        const int   ebase1 = i1p * (29 - i1p) / 2 - 1;  // e1 = ebase1 + i1q

        float* orow = out + b * OUTB + p * 256;

#pragma unroll
        for (int s = 0; s < 4; s++) {
            const int q0   = s * 64 + tq * 4;
            const int i2q  = q0 >> 4;
            const int i1q0 = q0 & 15;

            int e2ok = 0;
            if (i2p < i2q) {
                const int e2 = i2p * (29 - i2p) / 2 + i2q - 1;
                e2ok = boths[e2];
            }
            const float c_p2 = P2s[i2q * 16 + i1p];     // P2[i2q,i1p]

            float4 v;
            float* vp = &v.x;
#pragma unroll
            for (int k = 0; k < 4; k++) {
                const int i1q = i1q0 + k;
                float val = (i2q == i2p && i1q == i1p) ? mps[i1p] : 0.f;
                if (e2ok && i1p < i1q && boths[ebase1 + i1q])
                    val += a_p1 + P2s[i2p * 16 + i1q] + c_p2
                         + P1s[i2q * 16 + i1q];
                vp[k] = val;
            }
            *reinterpret_cast<float4*>(orow + q0) = v;
        }
    }
}

extern "C" void kernel_launch(void* const* d_in, const int* in_sizes, int n_in,
                              void* d_out, int out_size) {
    const int*   As   = (const int*)d_in[0];
    const int*   At   = (const int*)d_in[1];
    const float* Fs   = (const float*)d_in[2];
    const float* Ft   = (const float*)d_in[3];
    const float* Us   = (const float*)d_in[4];
    const float* Ut   = (const float*)d_in[5];
    const float* lam1 = (const float*)d_in[6];
    const float* lam2 = (const float*)d_in[7];
    float* out = (float*)d_out;

    kFused<<<GRID, 256>>>(Fs, Ft, Us, Ut, As, At, lam1, lam2, out);
}